// round 3
// baseline (speedup 1.0000x reference)
#include <cuda_runtime.h>
#include <cstdint>
#include <cstddef>

#define BB 64
#define LL 1024
#define HH 64
#define LM1 1023

// Scratch (device globals are the allowed scratch mechanism)
__device__ float g_k   [BB * LM1 * HH];   // raw (unnormalized) keys
__device__ float g_v   [BB * LM1 * HH];
__device__ float g_kinv[BB * LM1];        // 1/max(||k||, 1e-12)
__device__ float g_ven [BB * LM1];        // 0.16 * ||v||^2  (gate threshold)
__device__ float g_q   [BB * HH];

// Packed f32x2 FMA (Blackwell FFMA2 path; PTX fma.rn.f32x2)
__device__ __forceinline__ float2 fma2(float2 a, float2 b, float2 c) {
    float2 d;
    asm("fma.rn.f32x2 %0, %1, %2, %3;"
        : "=l"(*reinterpret_cast<unsigned long long*>(&d))
        : "l"(*reinterpret_cast<unsigned long long*>(&a)),
          "l"(*reinterpret_cast<unsigned long long*>(&b)),
          "l"(*reinterpret_cast<unsigned long long*>(&c)));
    return d;
}

// ---------------------------------------------------------------------------
// Kernel 1: per-token embed -> FF -> residual -> LayerNorm -> k/v/q proj.
// One thread per token; weights transposed in dynamic shared memory.
// ---------------------------------------------------------------------------
__global__ __launch_bounds__(256, 1)
void k_tokens(const int*   __restrict__ seq,
              const float* __restrict__ embedW,
              const float* __restrict__ W1,   // [64][128]
              const float* __restrict__ b1,   // [128]
              const float* __restrict__ W2,   // [128][64]
              const float* __restrict__ b2,   // [64]
              const float* __restrict__ lng,
              const float* __restrict__ lnb,
              const float* __restrict__ kpW,  // [64][64]
              const float* __restrict__ vpW,
              const float* __restrict__ qpW)
{
    extern __shared__ float sm[];
    float* sW1t = sm;             // [128][64]  (transposed W1)
    float* sW2  = sm + 8192;      // [128][64]  (as-is)
    float* sKpT = sm + 16384;     // [64][64]   (transposed)
    float* sVpT = sm + 20480;
    float* sQpT = sm + 24576;
    float* sB1  = sm + 28672;     // 128
    float* sB2  = sm + 28800;     // 64
    float* sG   = sm + 28864;     // 64
    float* sBt  = sm + 28928;     // 64

    const int tid = threadIdx.x;
    for (int idx = tid; idx < 8192; idx += 256) {
        int i = idx >> 7, j = idx & 127;      // W1[i][j]
        sW1t[j * 64 + i] = W1[idx];
    }
    for (int idx = tid; idx < 8192; idx += 256) sW2[idx] = W2[idx];
    for (int idx = tid; idx < 4096; idx += 256) {
        int i = idx >> 6, c = idx & 63;
        sKpT[c * 64 + i] = kpW[idx];
        sVpT[c * 64 + i] = vpW[idx];
        sQpT[c * 64 + i] = qpW[idx];
    }
    if (tid < 128) sB1[tid] = b1[tid];
    if (tid < 64) { sB2[tid] = b2[tid]; sG[tid] = lng[tid]; sBt[tid] = lnb[tid]; }
    __syncthreads();

    const int token = blockIdx.x * 256 + tid;
    const int b = token >> 10;
    const int t = token & 1023;
    const int sidx = seq[token];

    float2 h2[32];
    {
        const float4* e4 = reinterpret_cast<const float4*>(embedW + (sidx << 6));
        #pragma unroll
        for (int k = 0; k < 16; k++) {
            float4 w = e4[k];
            h2[2 * k]     = make_float2(w.x, w.y);
            h2[2 * k + 1] = make_float2(w.z, w.w);
        }
    }

    // FF: stream over hidden j, accumulate ff2 in acc
    float2 acc[32];
    #pragma unroll
    for (int k = 0; k < 32; k++) acc[k] = make_float2(sB2[2 * k], sB2[2 * k + 1]);

    for (int j = 0; j < 128; j++) {
        const float4* w1 = reinterpret_cast<const float4*>(sW1t + (j << 6));
        float2 p0 = make_float2(0.f, 0.f), p1 = p0, p2 = p0, p3 = p0;
        #pragma unroll
        for (int k = 0; k < 16; k += 2) {
            float4 wa = w1[k];
            float4 wb = w1[k + 1];
            p0 = fma2(h2[2 * k],     make_float2(wa.x, wa.y), p0);
            p1 = fma2(h2[2 * k + 1], make_float2(wa.z, wa.w), p1);
            p2 = fma2(h2[2 * k + 2], make_float2(wb.x, wb.y), p2);
            p3 = fma2(h2[2 * k + 3], make_float2(wb.z, wb.w), p3);
        }
        float sj = ((p0.x + p0.y) + (p1.x + p1.y)) + ((p2.x + p2.y) + (p3.x + p3.y)) + sB1[j];
        sj = fmaxf(sj, 0.0f);
        float2 s2 = make_float2(sj, sj);
        const float4* w2 = reinterpret_cast<const float4*>(sW2 + (j << 6));
        #pragma unroll
        for (int k = 0; k < 16; k++) {
            float4 w = w2[k];
            acc[2 * k]     = fma2(s2, make_float2(w.x, w.y), acc[2 * k]);
            acc[2 * k + 1] = fma2(s2, make_float2(w.z, w.w), acc[2 * k + 1]);
        }
    }

    // x = h + ff; LayerNorm (whole token in-thread: no cross-thread reductions)
    #pragma unroll
    for (int k = 0; k < 32; k++) { h2[k].x += acc[k].x; h2[k].y += acc[k].y; }
    float2 s = make_float2(0.f, 0.f);
    #pragma unroll
    for (int k = 0; k < 32; k++) { s.x += h2[k].x; s.y += h2[k].y; }
    const float mu = (s.x + s.y) * (1.0f / 64.0f);
    float2 vs = make_float2(0.f, 0.f);
    #pragma unroll
    for (int k = 0; k < 32; k++) {
        float dx = h2[k].x - mu, dy = h2[k].y - mu;
        vs.x += dx * dx; vs.y += dy * dy;
    }
    const float var = (vs.x + vs.y) * (1.0f / 64.0f);
    const float inv = 1.0f / sqrtf(var + 1e-5f);
    #pragma unroll
    for (int k = 0; k < 32; k++) {
        h2[k].x = (h2[k].x - mu) * inv * sG[2 * k]     + sBt[2 * k];
        h2[k].y = (h2[k].y - mu) * inv * sG[2 * k + 1] + sBt[2 * k + 1];
    }

    auto dot64 = [&](const float* wt) -> float {
        const float4* w4 = reinterpret_cast<const float4*>(wt);
        float2 p0 = make_float2(0.f, 0.f), p1 = p0, p2 = p0, p3 = p0;
        #pragma unroll
        for (int k = 0; k < 16; k += 2) {
            float4 wa = w4[k];
            float4 wb = w4[k + 1];
            p0 = fma2(h2[2 * k],     make_float2(wa.x, wa.y), p0);
            p1 = fma2(h2[2 * k + 1], make_float2(wa.z, wa.w), p1);
            p2 = fma2(h2[2 * k + 2], make_float2(wb.x, wb.y), p2);
            p3 = fma2(h2[2 * k + 3], make_float2(wb.z, wb.w), p3);
        }
        return ((p0.x + p0.y) + (p1.x + p1.y)) + ((p2.x + p2.y) + (p3.x + p3.y));
    };

    if (t < LM1) {
        const size_t base = ((size_t)(b * LM1 + t)) << 6;
        float nk = 0.f;
        for (int c = 0; c < 64; c += 4) {
            float4 o;
            o.x = dot64(sKpT + (c << 6));
            o.y = dot64(sKpT + ((c + 1) << 6));
            o.z = dot64(sKpT + ((c + 2) << 6));
            o.w = dot64(sKpT + ((c + 3) << 6));
            nk += o.x * o.x + o.y * o.y + o.z * o.z + o.w * o.w;
            *reinterpret_cast<float4*>(g_k + base + c) = o;
        }
        g_kinv[b * LM1 + t] = 1.0f / fmaxf(sqrtf(nk), 1e-12f);
        float nv = 0.f;
        for (int c = 0; c < 64; c += 4) {
            float4 o;
            o.x = dot64(sVpT + (c << 6));
            o.y = dot64(sVpT + ((c + 1) << 6));
            o.z = dot64(sVpT + ((c + 2) << 6));
            o.w = dot64(sVpT + ((c + 3) << 6));
            nv += o.x * o.x + o.y * o.y + o.z * o.z + o.w * o.w;
            *reinterpret_cast<float4*>(g_v + base + c) = o;
        }
        g_ven[b * LM1 + t] = 0.16f * nv;
    } else {
        for (int c = 0; c < 64; c += 4) {
            float4 o;
            o.x = dot64(sQpT + (c << 6));
            o.y = dot64(sQpT + ((c + 1) << 6));
            o.z = dot64(sQpT + ((c + 2) << 6));
            o.w = dot64(sQpT + ((c + 3) << 6));
            *reinterpret_cast<float4*>(g_q + (b << 6) + c) = o;
        }
    }
}

// ---------------------------------------------------------------------------
// Kernel 2: sequential gated fast-weight scan + epilogue.
// One CTA per batch, 64 threads; thread i owns M row i (32 x float2 regs).
// One barrier per step; 4-hop shfl + float4 partial slot for the gate
// reduction; branchless rank-1 update; prefetch distance 2.
// ---------------------------------------------------------------------------
__global__ __launch_bounds__(64, 1)
void k_scan(const float* __restrict__ rpW,
            const float* __restrict__ rpb,
            const float* __restrict__ outW,
            const float* __restrict__ outb,
            float* __restrict__ out)
{
    __shared__ float  skn[2][64];   // normalized key, double-buffered by parity
    __shared__ float4 sred4[2];     // 4 partial sums (2 per warp), double-buffered
    __shared__ float  sv[64];

    const int i = threadIdx.x;
    const int b = blockIdx.x;
    const int lane = i & 31, w = i >> 5;

    float2 M[32];
    #pragma unroll
    for (int k = 0; k < 32; k++) M[k] = make_float2(0.f, 0.f);

    const size_t base = (size_t)b * LM1 * 64;

    // ---- pipeline prologue: step 0 published, step 1 staged --------------
    float vcur = g_v[base + i];
    float vencur = g_ven[b * LM1];
    {
        float k0 = g_k[base + i];
        float ki0 = g_kinv[b * LM1];
        skn[0][i] = k0 * ki0;
    }
    float kraw1 = g_k[base + 64 + i];
    float v1    = g_v[base + 64 + i];
    float kinv1 = g_kinv[b * LM1 + 1];
    float ven1  = g_ven[b * LM1 + 1];
    __syncthreads();

    for (int t = 0; t < LM1; t++) {
        const int pb = t & 1;

        // prefetch step t+2 (L2-resident; ~2 steps of latency budget)
        float k2 = 0.f, v2 = 0.f, ki2 = 0.f, ven2 = 0.f;
        if (t + 2 < LM1) {
            const size_t o = base + (size_t)(t + 2) * 64 + i;
            k2   = g_k[o];
            v2   = g_v[o];
            ki2  = g_kinv[b * LM1 + t + 2];
            ven2 = g_ven[b * LM1 + t + 2];
        }

        // snapshot kn (broadcast LDS.128; used by matvec AND update)
        float4 kr[16];
        {
            const float4* k4 = reinterpret_cast<const float4*>(skn[pb]);
            #pragma unroll
            for (int k = 0; k < 16; k++) kr[k] = k4[k];
        }

        // vp_i = M[i,:] . kn
        float2 p0 = make_float2(0.f, 0.f), p1 = p0, p2 = p0, p3 = p0;
        #pragma unroll
        for (int k = 0; k < 16; k += 2) {
            p0 = fma2(M[2 * k],     make_float2(kr[k].x,     kr[k].y),     p0);
            p1 = fma2(M[2 * k + 1], make_float2(kr[k].z,     kr[k].w),     p1);
            p2 = fma2(M[2 * k + 2], make_float2(kr[k + 1].x, kr[k + 1].y), p2);
            p3 = fma2(M[2 * k + 3], make_float2(kr[k + 1].z, kr[k + 1].w), p3);
        }
        const float vp = ((p0.x + p0.y) + (p1.x + p1.y)) + ((p2.x + p2.y) + (p3.x + p3.y));
        const float d = vcur - vp;

        // gate fires iff sum(d^2) > 0.16*||v||^2 (precomputed)
        float z = d * d;
        z += __shfl_xor_sync(0xffffffffu, z, 1);
        z += __shfl_xor_sync(0xffffffffu, z, 2);
        z += __shfl_xor_sync(0xffffffffu, z, 4);
        z += __shfl_xor_sync(0xffffffffu, z, 8);
        // lanes 0 and 16 hold 16-lane group sums
        if ((lane & 15) == 0)
            reinterpret_cast<float*>(&sred4[pb])[w * 2 + (lane >> 4)] = z;

        // publish next step's normalized key BEFORE the single barrier
        if (t + 1 < LM1) skn[pb ^ 1][i] = kraw1 * kinv1;

        __syncthreads();                      // the ONLY barrier per step

        const float4 r4 = sred4[pb];
        const float zt = (r4.x + r4.y) + (r4.z + r4.w);
        const float dg = (zt > vencur) ? d : 0.0f;   // branchless gate
        const float2 d2 = make_float2(dg, dg);
        #pragma unroll
        for (int k = 0; k < 16; k++) {
            M[2 * k]     = fma2(d2, make_float2(kr[k].x, kr[k].y), M[2 * k]);
            M[2 * k + 1] = fma2(d2, make_float2(kr[k].z, kr[k].w), M[2 * k + 1]);
        }

        // shift pipeline
        vcur = v1; vencur = ven1;
        kraw1 = k2; v1 = v2; kinv1 = ki2; ven1 = ven2;
    }

    // -------- epilogue: r = (M q) @ rp_W + rp_b ; out = r @ out_W + out_b ---
    __syncthreads();
    skn[0][i] = g_q[(b << 6) + i];
    __syncthreads();
    float mq;
    {
        const float4* k4 = reinterpret_cast<const float4*>(skn[0]);
        float2 p0 = make_float2(0.f, 0.f), p1 = p0, p2 = p0, p3 = p0;
        #pragma unroll
        for (int k = 0; k < 16; k += 2) {
            float4 wa = k4[k];
            float4 wb = k4[k + 1];
            p0 = fma2(M[2 * k],     make_float2(wa.x, wa.y), p0);
            p1 = fma2(M[2 * k + 1], make_float2(wa.z, wa.w), p1);
            p2 = fma2(M[2 * k + 2], make_float2(wb.x, wb.y), p2);
            p3 = fma2(M[2 * k + 3], make_float2(wb.z, wb.w), p3);
        }
        mq = ((p0.x + p0.y) + (p1.x + p1.y)) + ((p2.x + p2.y) + (p3.x + p3.y));
    }
    __syncthreads();
    sv[i] = mq;
    __syncthreads();
    float r = rpb[i];
    for (int j = 0; j < 64; j++) r = fmaf(sv[j], rpW[j * 64 + i], r);
    __syncthreads();
    sv[i] = r;
    __syncthreads();
    float o = outb[i];
    for (int j = 0; j < 64; j++) o = fmaf(sv[j], outW[j * 64 + i], o);
    out[(b << 6) + i] = o;
}

// ---------------------------------------------------------------------------
extern "C" void kernel_launch(void* const* d_in, const int* in_sizes, int n_in,
                              void* d_out, int out_size)
{
    const int*   seq    = (const int*)  d_in[0];
    const float* embedW = (const float*)d_in[1];
    const float* W1     = (const float*)d_in[2];
    const float* b1     = (const float*)d_in[3];
    const float* W2     = (const float*)d_in[4];
    const float* b2     = (const float*)d_in[5];
    const float* lng    = (const float*)d_in[6];
    const float* lnb    = (const float*)d_in[7];
    const float* kpW    = (const float*)d_in[8];
    const float* vpW    = (const float*)d_in[9];
    const float* qpW    = (const float*)d_in[10];
    const float* rpW    = (const float*)d_in[11];
    const float* rpb    = (const float*)d_in[12];
    const float* outW   = (const float*)d_in[13];
    const float* outb   = (const float*)d_in[14];
    float* out = (float*)d_out;

    const int smem = 28992 * (int)sizeof(float);   // 115968 B
    cudaFuncSetAttribute(k_tokens, cudaFuncAttributeMaxDynamicSharedMemorySize, smem);

    k_tokens<<<256, 256, smem>>>(seq, embedW, W1, b1, W2, b2, lng, lnb, kpW, vpW, qpW);
    k_scan<<<64, 64>>>(rpW, rpb, outW, outb, out);
}

// round 4
// speedup vs baseline: 1.0673x; 1.0673x over previous
#include <cuda_runtime.h>
#include <cstdint>
#include <cstddef>

#define BB 64
#define LL 1024
#define HH 64
#define LM1 1023

// Scratch (device globals are the allowed scratch mechanism).
// Padded by 2 steps so the scan's distance-2 prefetch needs no bounds check.
__device__ float g_k  [BB * LM1 * HH + 2 * HH];   // pre-normalized keys
__device__ float g_v  [BB * LM1 * HH + 2 * HH];
__device__ float g_ven[BB * LM1 + 2];             // 0.16 * ||v||^2
__device__ float g_q  [BB * HH];

// Packed f32x2 FMA (Blackwell FFMA2 path; PTX fma.rn.f32x2)
__device__ __forceinline__ float2 fma2(float2 a, float2 b, float2 c) {
    float2 d;
    asm("fma.rn.f32x2 %0, %1, %2, %3;"
        : "=l"(*reinterpret_cast<unsigned long long*>(&d))
        : "l"(*reinterpret_cast<unsigned long long*>(&a)),
          "l"(*reinterpret_cast<unsigned long long*>(&b)),
          "l"(*reinterpret_cast<unsigned long long*>(&c)));
    return d;
}

// ---------------------------------------------------------------------------
// Kernel 1: per-token embed -> FF -> residual -> LayerNorm -> k/v/q proj.
// One thread per token; weights transposed in dynamic shared memory.
// Stores NORMALIZED keys and the gate threshold 0.16*||v||^2.
// ---------------------------------------------------------------------------
__global__ __launch_bounds__(256, 1)
void k_tokens(const int*   __restrict__ seq,
              const float* __restrict__ embedW,
              const float* __restrict__ W1,   // [64][128]
              const float* __restrict__ b1,   // [128]
              const float* __restrict__ W2,   // [128][64]
              const float* __restrict__ b2,   // [64]
              const float* __restrict__ lng,
              const float* __restrict__ lnb,
              const float* __restrict__ kpW,  // [64][64]
              const float* __restrict__ vpW,
              const float* __restrict__ qpW)
{
    extern __shared__ float sm[];
    float* sW1t = sm;             // [128][64]  (transposed W1)
    float* sW2  = sm + 8192;      // [128][64]  (as-is)
    float* sKpT = sm + 16384;     // [64][64]   (transposed)
    float* sVpT = sm + 20480;
    float* sQpT = sm + 24576;
    float* sB1  = sm + 28672;     // 128
    float* sB2  = sm + 28800;     // 64
    float* sG   = sm + 28864;     // 64
    float* sBt  = sm + 28928;     // 64

    const int tid = threadIdx.x;
    for (int idx = tid; idx < 8192; idx += 256) {
        int i = idx >> 7, j = idx & 127;      // W1[i][j]
        sW1t[j * 64 + i] = W1[idx];
    }
    for (int idx = tid; idx < 8192; idx += 256) sW2[idx] = W2[idx];
    for (int idx = tid; idx < 4096; idx += 256) {
        int i = idx >> 6, c = idx & 63;
        sKpT[c * 64 + i] = kpW[idx];
        sVpT[c * 64 + i] = vpW[idx];
        sQpT[c * 64 + i] = qpW[idx];
    }
    if (tid < 128) sB1[tid] = b1[tid];
    if (tid < 64) { sB2[tid] = b2[tid]; sG[tid] = lng[tid]; sBt[tid] = lnb[tid]; }
    __syncthreads();

    const int token = blockIdx.x * 256 + tid;
    const int b = token >> 10;
    const int t = token & 1023;
    const int sidx = seq[token];

    float2 h2[32];
    {
        const float4* e4 = reinterpret_cast<const float4*>(embedW + (sidx << 6));
        #pragma unroll
        for (int k = 0; k < 16; k++) {
            float4 w = e4[k];
            h2[2 * k]     = make_float2(w.x, w.y);
            h2[2 * k + 1] = make_float2(w.z, w.w);
        }
    }

    // FF: stream over hidden j, accumulate ff2 in acc
    float2 acc[32];
    #pragma unroll
    for (int k = 0; k < 32; k++) acc[k] = make_float2(sB2[2 * k], sB2[2 * k + 1]);

    for (int j = 0; j < 128; j++) {
        const float4* w1 = reinterpret_cast<const float4*>(sW1t + (j << 6));
        float2 p0 = make_float2(0.f, 0.f), p1 = p0, p2 = p0, p3 = p0;
        #pragma unroll
        for (int k = 0; k < 16; k += 2) {
            float4 wa = w1[k];
            float4 wb = w1[k + 1];
            p0 = fma2(h2[2 * k],     make_float2(wa.x, wa.y), p0);
            p1 = fma2(h2[2 * k + 1], make_float2(wa.z, wa.w), p1);
            p2 = fma2(h2[2 * k + 2], make_float2(wb.x, wb.y), p2);
            p3 = fma2(h2[2 * k + 3], make_float2(wb.z, wb.w), p3);
        }
        float sj = ((p0.x + p0.y) + (p1.x + p1.y)) + ((p2.x + p2.y) + (p3.x + p3.y)) + sB1[j];
        sj = fmaxf(sj, 0.0f);
        float2 s2 = make_float2(sj, sj);
        const float4* w2 = reinterpret_cast<const float4*>(sW2 + (j << 6));
        #pragma unroll
        for (int k = 0; k < 16; k++) {
            float4 w = w2[k];
            acc[2 * k]     = fma2(s2, make_float2(w.x, w.y), acc[2 * k]);
            acc[2 * k + 1] = fma2(s2, make_float2(w.z, w.w), acc[2 * k + 1]);
        }
    }

    // x = h + ff; LayerNorm (whole token in-thread)
    #pragma unroll
    for (int k = 0; k < 32; k++) { h2[k].x += acc[k].x; h2[k].y += acc[k].y; }
    float2 s = make_float2(0.f, 0.f);
    #pragma unroll
    for (int k = 0; k < 32; k++) { s.x += h2[k].x; s.y += h2[k].y; }
    const float mu = (s.x + s.y) * (1.0f / 64.0f);
    float2 vs = make_float2(0.f, 0.f);
    #pragma unroll
    for (int k = 0; k < 32; k++) {
        float dx = h2[k].x - mu, dy = h2[k].y - mu;
        vs.x += dx * dx; vs.y += dy * dy;
    }
    const float var = (vs.x + vs.y) * (1.0f / 64.0f);
    const float inv = 1.0f / sqrtf(var + 1e-5f);
    #pragma unroll
    for (int k = 0; k < 32; k++) {
        h2[k].x = (h2[k].x - mu) * inv * sG[2 * k]     + sBt[2 * k];
        h2[k].y = (h2[k].y - mu) * inv * sG[2 * k + 1] + sBt[2 * k + 1];
    }

    auto dot64 = [&](const float* wt) -> float {
        const float4* w4 = reinterpret_cast<const float4*>(wt);
        float2 p0 = make_float2(0.f, 0.f), p1 = p0, p2 = p0, p3 = p0;
        #pragma unroll
        for (int k = 0; k < 16; k += 2) {
            float4 wa = w4[k];
            float4 wb = w4[k + 1];
            p0 = fma2(h2[2 * k],     make_float2(wa.x, wa.y), p0);
            p1 = fma2(h2[2 * k + 1], make_float2(wa.z, wa.w), p1);
            p2 = fma2(h2[2 * k + 2], make_float2(wb.x, wb.y), p2);
            p3 = fma2(h2[2 * k + 3], make_float2(wb.z, wb.w), p3);
        }
        return ((p0.x + p0.y) + (p1.x + p1.y)) + ((p2.x + p2.y) + (p3.x + p3.y));
    };

    if (t < LM1) {
        const size_t base = ((size_t)(b * LM1 + t)) << 6;
        // keys: compute all 64, then store NORMALIZED
        float4 kk[16];
        float nk = 0.f;
        #pragma unroll
        for (int c4 = 0; c4 < 16; c4++) {
            int c = c4 * 4;
            float4 o;
            o.x = dot64(sKpT + (c << 6));
            o.y = dot64(sKpT + ((c + 1) << 6));
            o.z = dot64(sKpT + ((c + 2) << 6));
            o.w = dot64(sKpT + ((c + 3) << 6));
            nk += o.x * o.x + o.y * o.y + o.z * o.z + o.w * o.w;
            kk[c4] = o;
        }
        const float kinv = 1.0f / fmaxf(sqrtf(nk), 1e-12f);
        #pragma unroll
        for (int c4 = 0; c4 < 16; c4++) {
            float4 o = kk[c4];
            o.x *= kinv; o.y *= kinv; o.z *= kinv; o.w *= kinv;
            *reinterpret_cast<float4*>(g_k + base + c4 * 4) = o;
        }
        float nv = 0.f;
        for (int c = 0; c < 64; c += 4) {
            float4 o;
            o.x = dot64(sVpT + (c << 6));
            o.y = dot64(sVpT + ((c + 1) << 6));
            o.z = dot64(sVpT + ((c + 2) << 6));
            o.w = dot64(sVpT + ((c + 3) << 6));
            nv += o.x * o.x + o.y * o.y + o.z * o.z + o.w * o.w;
            *reinterpret_cast<float4*>(g_v + base + c) = o;
        }
        g_ven[b * LM1 + t] = 0.16f * nv;
    } else {
        for (int c = 0; c < 64; c += 4) {
            float4 o;
            o.x = dot64(sQpT + (c << 6));
            o.y = dot64(sQpT + ((c + 1) << 6));
            o.z = dot64(sQpT + ((c + 2) << 6));
            o.w = dot64(sQpT + ((c + 3) << 6));
            *reinterpret_cast<float4*>(g_q + (b << 6) + c) = o;
        }
    }
}

// ---------------------------------------------------------------------------
// Kernel 2: sequential gated fast-weight scan + epilogue.
// SINGLE WARP per CTA (32 threads); thread l owns M rows 2l and 2l+1.
// Gate reduction is fully intra-warp (5-hop shfl) -> zero bar.sync per step.
// Branch-free loop body (padded scratch); keys arrive pre-normalized.
// ---------------------------------------------------------------------------
__global__ __launch_bounds__(32, 1)
void k_scan(const float* __restrict__ rpW,
            const float* __restrict__ rpb,
            const float* __restrict__ outW,
            const float* __restrict__ outb,
            float* __restrict__ out)
{
    __shared__ float skn[2][64];   // current/next normalized key
    __shared__ float sv[64];

    const int l = threadIdx.x;          // 0..31
    const int b = blockIdx.x;

    float2 M0[32], M1[32];              // rows 2l, 2l+1 (float2 over columns)
    #pragma unroll
    for (int c = 0; c < 32; c++) { M0[c] = make_float2(0.f, 0.f); M1[c] = M0[c]; }

    const size_t base = (size_t)b * LM1 * 64;
    const int    sb   = b * LM1;

    // ---- prologue: publish key 0, stage step 1 ---------------------------
    float2 vcur = *reinterpret_cast<const float2*>(&g_v[base + 2 * l]);
    float  vencur = g_ven[sb];
    *reinterpret_cast<float2*>(&skn[0][2 * l]) =
        *reinterpret_cast<const float2*>(&g_k[base + 2 * l]);
    float2 k1 = *reinterpret_cast<const float2*>(&g_k[base + 64 + 2 * l]);
    float2 v1 = *reinterpret_cast<const float2*>(&g_v[base + 64 + 2 * l]);
    float  ven1 = g_ven[sb + 1];
    __syncwarp();

    for (int t = 0; t < LM1; t++) {
        const int pb = t & 1;

        // publish next key; prefetch t+2 (arrays padded: no bounds checks)
        *reinterpret_cast<float2*>(&skn[pb ^ 1][2 * l]) = k1;
        const size_t o2 = base + (size_t)(t + 2) * 64 + 2 * l;
        const float2 k2 = *reinterpret_cast<const float2*>(&g_k[o2]);
        const float2 v2 = *reinterpret_cast<const float2*>(&g_v[o2]);
        const float  ven2 = g_ven[sb + t + 2];
        __syncwarp();

        const float4* kp = reinterpret_cast<const float4*>(skn[pb]);

        // matvec for both owned rows
        float2 p00 = make_float2(0.f, 0.f), p01 = p00, p10 = p00, p11 = p00;
        #pragma unroll
        for (int c = 0; c < 16; c++) {
            const float4 kv = kp[c];
            const float2 ka = make_float2(kv.x, kv.y);
            const float2 kb = make_float2(kv.z, kv.w);
            p00 = fma2(M0[2 * c],     ka, p00);
            p01 = fma2(M0[2 * c + 1], kb, p01);
            p10 = fma2(M1[2 * c],     ka, p10);
            p11 = fma2(M1[2 * c + 1], kb, p11);
        }
        const float d0 = vcur.x - ((p00.x + p00.y) + (p01.x + p01.y));
        const float d1 = vcur.y - ((p10.x + p10.y) + (p11.x + p11.y));

        // intra-warp gate reduction: sum over all 64 components
        float z = fmaf(d0, d0, d1 * d1);
        z += __shfl_xor_sync(0xffffffffu, z, 1);
        z += __shfl_xor_sync(0xffffffffu, z, 2);
        z += __shfl_xor_sync(0xffffffffu, z, 4);
        z += __shfl_xor_sync(0xffffffffu, z, 8);
        z += __shfl_xor_sync(0xffffffffu, z, 16);

        const bool g = (z > vencur);
        const float dg0 = g ? d0 : 0.0f;
        const float dg1 = g ? d1 : 0.0f;
        const float2 g0 = make_float2(dg0, dg0);
        const float2 g1 = make_float2(dg1, dg1);
        #pragma unroll
        for (int c = 0; c < 16; c++) {
            const float4 kv = kp[c];
            const float2 ka = make_float2(kv.x, kv.y);
            const float2 kb = make_float2(kv.z, kv.w);
            M0[2 * c]     = fma2(g0, ka, M0[2 * c]);
            M0[2 * c + 1] = fma2(g0, kb, M0[2 * c + 1]);
            M1[2 * c]     = fma2(g1, ka, M1[2 * c]);
            M1[2 * c + 1] = fma2(g1, kb, M1[2 * c + 1]);
        }

        // rotate pipeline
        vcur = v1; vencur = ven1;
        k1 = k2; v1 = v2; ven1 = ven2;
    }

    // -------- epilogue: r = (M q) @ rp_W + rp_b ; out = r @ out_W + out_b ---
    __syncwarp();
    *reinterpret_cast<float2*>(&skn[0][2 * l]) =
        *reinterpret_cast<const float2*>(&g_q[(b << 6) + 2 * l]);
    __syncwarp();
    {
        const float4* qp = reinterpret_cast<const float4*>(skn[0]);
        float2 p00 = make_float2(0.f, 0.f), p01 = p00, p10 = p00, p11 = p00;
        #pragma unroll
        for (int c = 0; c < 16; c++) {
            const float4 kv = qp[c];
            const float2 ka = make_float2(kv.x, kv.y);
            const float2 kb = make_float2(kv.z, kv.w);
            p00 = fma2(M0[2 * c],     ka, p00);
            p01 = fma2(M0[2 * c + 1], kb, p01);
            p10 = fma2(M1[2 * c],     ka, p10);
            p11 = fma2(M1[2 * c + 1], kb, p11);
        }
        sv[2 * l]     = (p00.x + p00.y) + (p01.x + p01.y);
        sv[2 * l + 1] = (p10.x + p10.y) + (p11.x + p11.y);
    }
    __syncwarp();
    {
        float2 r = *reinterpret_cast<const float2*>(&rpb[2 * l]);
        for (int j = 0; j < 64; j++) {
            const float2 w = *reinterpret_cast<const float2*>(&rpW[j * 64 + 2 * l]);
            const float s = sv[j];
            r.x = fmaf(s, w.x, r.x);
            r.y = fmaf(s, w.y, r.y);
        }
        __syncwarp();
        sv[2 * l] = r.x; sv[2 * l + 1] = r.y;
    }
    __syncwarp();
    {
        float2 o = *reinterpret_cast<const float2*>(&outb[2 * l]);
        for (int j = 0; j < 64; j++) {
            const float2 w = *reinterpret_cast<const float2*>(&outW[j * 64 + 2 * l]);
            const float s = sv[j];
            o.x = fmaf(s, w.x, o.x);
            o.y = fmaf(s, w.y, o.y);
        }
        *reinterpret_cast<float2*>(&out[(b << 6) + 2 * l]) = o;
    }
}

// ---------------------------------------------------------------------------
extern "C" void kernel_launch(void* const* d_in, const int* in_sizes, int n_in,
                              void* d_out, int out_size)
{
    const int*   seq    = (const int*)  d_in[0];
    const float* embedW = (const float*)d_in[1];
    const float* W1     = (const float*)d_in[2];
    const float* b1     = (const float*)d_in[3];
    const float* W2     = (const float*)d_in[4];
    const float* b2     = (const float*)d_in[5];
    const float* lng    = (const float*)d_in[6];
    const float* lnb    = (const float*)d_in[7];
    const float* kpW    = (const float*)d_in[8];
    const float* vpW    = (const float*)d_in[9];
    const float* qpW    = (const float*)d_in[10];
    const float* rpW    = (const float*)d_in[11];
    const float* rpb    = (const float*)d_in[12];
    const float* outW   = (const float*)d_in[13];
    const float* outb   = (const float*)d_in[14];
    float* out = (float*)d_out;

    const int smem = 28992 * (int)sizeof(float);   // 115968 B
    cudaFuncSetAttribute(k_tokens, cudaFuncAttributeMaxDynamicSharedMemorySize, smem);

    k_tokens<<<256, 256, smem>>>(seq, embedW, W1, b1, W2, b2, lng, lnb, kpW, vpW, qpW);
    k_scan<<<64, 32>>>(rpW, rpb, outW, outb, out);
}

// round 5
// speedup vs baseline: 1.4557x; 1.3639x over previous
#include <cuda_runtime.h>
#include <cstdint>
#include <cstddef>

#define BB 64
#define LL 1024
#define HH 64
#define LM1 1023
#define CH 32            // scan staging chunk (steps)

// Scratch (device globals — the allowed scratch mechanism). Zero-initialized.
__device__ float g_k  [BB * LM1 * HH + 2 * HH];   // pre-normalized keys
__device__ float g_v  [BB * LM1 * HH + 2 * HH];
__device__ float g_ven[BB * 1024];                // 0.16*||v||^2, stride 1024 (16B-aligned chunks)
__device__ float g_gam[BB * 1024];                // gamma_t = kn_t . kn_{t+1}
__device__ float g_q  [BB * HH];

// Packed f32x2 FMA
__device__ __forceinline__ float2 fma2(float2 a, float2 b, float2 c) {
    float2 d;
    asm("fma.rn.f32x2 %0, %1, %2, %3;"
        : "=l"(*reinterpret_cast<unsigned long long*>(&d))
        : "l"(*reinterpret_cast<unsigned long long*>(&a)),
          "l"(*reinterpret_cast<unsigned long long*>(&b)),
          "l"(*reinterpret_cast<unsigned long long*>(&c)));
    return d;
}

__device__ __forceinline__ void cp16(uint32_t dst, const void* src) {
    asm volatile("cp.async.cg.shared.global [%0], [%1], 16;" :: "r"(dst), "l"(src));
}

// ---------------------------------------------------------------------------
// Kernel 1: per-token embed -> FF -> residual -> LayerNorm -> k/v/q proj.
// ---------------------------------------------------------------------------
__global__ __launch_bounds__(256, 1)
void k_tokens(const int*   __restrict__ seq,
              const float* __restrict__ embedW,
              const float* __restrict__ W1,
              const float* __restrict__ b1,
              const float* __restrict__ W2,
              const float* __restrict__ b2,
              const float* __restrict__ lng,
              const float* __restrict__ lnb,
              const float* __restrict__ kpW,
              const float* __restrict__ vpW,
              const float* __restrict__ qpW)
{
    extern __shared__ float sm[];
    float* sW1t = sm;             // [128][64]
    float* sW2  = sm + 8192;      // [128][64]
    float* sKpT = sm + 16384;     // [64][64] transposed
    float* sVpT = sm + 20480;
    float* sQpT = sm + 24576;
    float* sB1  = sm + 28672;
    float* sB2  = sm + 28800;
    float* sG   = sm + 28864;
    float* sBt  = sm + 28928;

    const int tid = threadIdx.x;
    for (int idx = tid; idx < 8192; idx += 256) {
        int i = idx >> 7, j = idx & 127;
        sW1t[j * 64 + i] = W1[idx];
    }
    for (int idx = tid; idx < 8192; idx += 256) sW2[idx] = W2[idx];
    for (int idx = tid; idx < 4096; idx += 256) {
        int i = idx >> 6, c = idx & 63;
        sKpT[c * 64 + i] = kpW[idx];
        sVpT[c * 64 + i] = vpW[idx];
        sQpT[c * 64 + i] = qpW[idx];
    }
    if (tid < 128) sB1[tid] = b1[tid];
    if (tid < 64) { sB2[tid] = b2[tid]; sG[tid] = lng[tid]; sBt[tid] = lnb[tid]; }
    __syncthreads();

    const int token = blockIdx.x * 256 + tid;
    const int b = token >> 10;
    const int t = token & 1023;
    const int sidx = seq[token];

    float2 h2[32];
    {
        const float4* e4 = reinterpret_cast<const float4*>(embedW + (sidx << 6));
        #pragma unroll
        for (int k = 0; k < 16; k++) {
            float4 w = e4[k];
            h2[2 * k]     = make_float2(w.x, w.y);
            h2[2 * k + 1] = make_float2(w.z, w.w);
        }
    }

    float2 acc[32];
    #pragma unroll
    for (int k = 0; k < 32; k++) acc[k] = make_float2(sB2[2 * k], sB2[2 * k + 1]);

    for (int j = 0; j < 128; j++) {
        const float4* w1 = reinterpret_cast<const float4*>(sW1t + (j << 6));
        float2 p0 = make_float2(0.f, 0.f), p1 = p0, p2 = p0, p3 = p0;
        #pragma unroll
        for (int k = 0; k < 16; k += 2) {
            float4 wa = w1[k];
            float4 wb = w1[k + 1];
            p0 = fma2(h2[2 * k],     make_float2(wa.x, wa.y), p0);
            p1 = fma2(h2[2 * k + 1], make_float2(wa.z, wa.w), p1);
            p2 = fma2(h2[2 * k + 2], make_float2(wb.x, wb.y), p2);
            p3 = fma2(h2[2 * k + 3], make_float2(wb.z, wb.w), p3);
        }
        float sj = ((p0.x + p0.y) + (p1.x + p1.y)) + ((p2.x + p2.y) + (p3.x + p3.y)) + sB1[j];
        sj = fmaxf(sj, 0.0f);
        float2 s2 = make_float2(sj, sj);
        const float4* w2 = reinterpret_cast<const float4*>(sW2 + (j << 6));
        #pragma unroll
        for (int k = 0; k < 16; k++) {
            float4 w = w2[k];
            acc[2 * k]     = fma2(s2, make_float2(w.x, w.y), acc[2 * k]);
            acc[2 * k + 1] = fma2(s2, make_float2(w.z, w.w), acc[2 * k + 1]);
        }
    }

    #pragma unroll
    for (int k = 0; k < 32; k++) { h2[k].x += acc[k].x; h2[k].y += acc[k].y; }
    float2 s = make_float2(0.f, 0.f);
    #pragma unroll
    for (int k = 0; k < 32; k++) { s.x += h2[k].x; s.y += h2[k].y; }
    const float mu = (s.x + s.y) * (1.0f / 64.0f);
    float2 vs = make_float2(0.f, 0.f);
    #pragma unroll
    for (int k = 0; k < 32; k++) {
        float dx = h2[k].x - mu, dy = h2[k].y - mu;
        vs.x += dx * dx; vs.y += dy * dy;
    }
    const float var = (vs.x + vs.y) * (1.0f / 64.0f);
    const float inv = 1.0f / sqrtf(var + 1e-5f);
    #pragma unroll
    for (int k = 0; k < 32; k++) {
        h2[k].x = (h2[k].x - mu) * inv * sG[2 * k]     + sBt[2 * k];
        h2[k].y = (h2[k].y - mu) * inv * sG[2 * k + 1] + sBt[2 * k + 1];
    }

    auto dot64 = [&](const float* wt) -> float {
        const float4* w4 = reinterpret_cast<const float4*>(wt);
        float2 p0 = make_float2(0.f, 0.f), p1 = p0, p2 = p0, p3 = p0;
        #pragma unroll
        for (int k = 0; k < 16; k += 2) {
            float4 wa = w4[k];
            float4 wb = w4[k + 1];
            p0 = fma2(h2[2 * k],     make_float2(wa.x, wa.y), p0);
            p1 = fma2(h2[2 * k + 1], make_float2(wa.z, wa.w), p1);
            p2 = fma2(h2[2 * k + 2], make_float2(wb.x, wb.y), p2);
            p3 = fma2(h2[2 * k + 3], make_float2(wb.z, wb.w), p3);
        }
        return ((p0.x + p0.y) + (p1.x + p1.y)) + ((p2.x + p2.y) + (p3.x + p3.y));
    };

    if (t < LM1) {
        const size_t base = ((size_t)(b * LM1 + t)) << 6;
        float4 kk[16];
        float nk = 0.f;
        #pragma unroll
        for (int c4 = 0; c4 < 16; c4++) {
            int c = c4 * 4;
            float4 o;
            o.x = dot64(sKpT + (c << 6));
            o.y = dot64(sKpT + ((c + 1) << 6));
            o.z = dot64(sKpT + ((c + 2) << 6));
            o.w = dot64(sKpT + ((c + 3) << 6));
            nk += o.x * o.x + o.y * o.y + o.z * o.z + o.w * o.w;
            kk[c4] = o;
        }
        const float kinv = 1.0f / fmaxf(sqrtf(nk), 1e-12f);
        #pragma unroll
        for (int c4 = 0; c4 < 16; c4++) {
            float4 o = kk[c4];
            o.x *= kinv; o.y *= kinv; o.z *= kinv; o.w *= kinv;
            *reinterpret_cast<float4*>(g_k + base + c4 * 4) = o;
        }
        float nv = 0.f;
        for (int c = 0; c < 64; c += 4) {
            float4 o;
            o.x = dot64(sVpT + (c << 6));
            o.y = dot64(sVpT + ((c + 1) << 6));
            o.z = dot64(sVpT + ((c + 2) << 6));
            o.w = dot64(sVpT + ((c + 3) << 6));
            nv += o.x * o.x + o.y * o.y + o.z * o.z + o.w * o.w;
            *reinterpret_cast<float4*>(g_v + base + c) = o;
        }
        g_ven[(b << 10) + t] = 0.16f * nv;
    } else {
        for (int c = 0; c < 64; c += 4) {
            float4 o;
            o.x = dot64(sQpT + (c << 6));
            o.y = dot64(sQpT + ((c + 1) << 6));
            o.z = dot64(sQpT + ((c + 2) << 6));
            o.w = dot64(sQpT + ((c + 3) << 6));
            *reinterpret_cast<float4*>(g_q + (b << 6) + c) = o;
        }
    }
}

// ---------------------------------------------------------------------------
// Kernel 1b: adjacent-key dots  gamma[b][t] = kn_t . kn_{t+1}  (off scan path)
// ---------------------------------------------------------------------------
__global__ __launch_bounds__(256, 1)
void k_gamma()
{
    const int idx = blockIdx.x * 256 + threadIdx.x;   // 64*1024 threads
    const int b = idx >> 10;
    const int t = idx & 1023;
    float g = 0.0f;
    if (t <= LM1 - 2) {
        const float4* a = reinterpret_cast<const float4*>(g_k + (((size_t)(b * LM1 + t)) << 6));
        const float4* c = a + 16;   // next token (contiguous)
        float s0 = 0.f, s1 = 0.f, s2 = 0.f, s3 = 0.f;
        #pragma unroll
        for (int k = 0; k < 16; k += 2) {
            float4 x0 = a[k],     y0 = c[k];
            float4 x1 = a[k + 1], y1 = c[k + 1];
            s0 = fmaf(x0.x, y0.x, fmaf(x0.y, y0.y, s0));
            s1 = fmaf(x0.z, y0.z, fmaf(x0.w, y0.w, s1));
            s2 = fmaf(x1.x, y1.x, fmaf(x1.y, y1.y, s2));
            s3 = fmaf(x1.z, y1.z, fmaf(x1.w, y1.w, s3));
        }
        g = (s0 + s1) + (s2 + s3);
    }
    g_gam[(b << 10) + t] = g;
}

// ---------------------------------------------------------------------------
// Kernel 2: gated fast-weight scan, lookahead-1 form + epilogue.
// 64 threads (2 warps), thread i owns M row i (float2 over columns).
//   pre_t     = M_{t-2} . kn_t           (batched, off serial path)
//   vp_t      = pre_t + gamma_{t-1}*gd_{t-1}   (1 fma — the serial path)
//   gate_t    : ||d_t||^2 > 0.16||v_t||^2 (tree + 1 bar)
//   M update with gd_{t-1} deferred into step t's batch phase.
// k/v/ven/gamma staged via cp.async chunks (CH steps), 2-chunk ring.
// ---------------------------------------------------------------------------
__global__ __launch_bounds__(64, 1)
void k_scan(const float* __restrict__ rpW,
            const float* __restrict__ rpb,
            const float* __restrict__ outW,
            const float* __restrict__ outb,
            float* __restrict__ out)
{
    __shared__ float sK[2 * CH][64];
    __shared__ float sV[2 * CH][64];
    __shared__ float sVen[2 * CH];
    __shared__ float sGam[2 * CH];
    __shared__ float sred[2][2];
    __shared__ float sq[64];
    __shared__ float sr[64];

    const int i = threadIdx.x;
    const int b = blockIdx.x;
    const int lane = i & 31, w = i >> 5;

    const size_t base = (size_t)b * LM1 * 64;
    const int vb = b << 10;

    const uint32_t aK   = (uint32_t)__cvta_generic_to_shared(&sK[0][0]);
    const uint32_t aV   = (uint32_t)__cvta_generic_to_shared(&sV[0][0]);
    const uint32_t aVen = (uint32_t)__cvta_generic_to_shared(&sVen[0]);
    const uint32_t aGam = (uint32_t)__cvta_generic_to_shared(&sGam[0]);

    // stage chunk q (steps q*CH .. q*CH+CH-1) into ring half (q&1)
    auto stage = [&](int q) {
        const int hb = (q & 1) * (CH * 64 * 4);        // byte offset in sK/sV
        const int hs = (q & 1) * (CH * 4);             // byte offset in sVen/sGam
        const char* gk = (const char*)(g_k + base) + ((size_t)q << 13);  // q*CH*64*4
        const char* gv = (const char*)(g_v + base) + ((size_t)q << 13);
        #pragma unroll
        for (int r = 0; r < 8; r++) {
            cp16(aK + hb + i * 16 + r * 1024, gk + i * 16 + r * 1024);
            cp16(aV + hb + i * 16 + r * 1024, gv + i * 16 + r * 1024);
        }
        if (i < 8) {
            cp16(aVen + hs + i * 16, (const char*)(g_ven + vb + q * CH) + i * 16);
        } else if (i < 16) {
            cp16(aGam + hs + (i - 8) * 16, (const char*)(g_gam + vb + q * CH) + (i - 8) * 16);
        }
        asm volatile("cp.async.commit_group;" ::: "memory");
    };

    float2 M[32];
    #pragma unroll
    for (int c = 0; c < 32; c++) M[c] = make_float2(0.f, 0.f);

    // ---- prologue: chunk 0 -----------------------------------------------
    stage(0);
    asm volatile("cp.async.wait_group 0;" ::: "memory");
    __syncthreads();

    // ---- peel step 0 (M = 0 -> vp = 0) -----------------------------------
    float vcur = sV[0][i];
    float vencur = sVen[0];
    float pre = 0.0f, gdp, gamp;
    {
        float d = vcur;
        float z = d * d;
        z += __shfl_xor_sync(0xffffffffu, z, 1);
        z += __shfl_xor_sync(0xffffffffu, z, 2);
        z += __shfl_xor_sync(0xffffffffu, z, 4);
        z += __shfl_xor_sync(0xffffffffu, z, 8);
        z += __shfl_xor_sync(0xffffffffu, z, 16);
        if (lane == 0) sred[0][w] = z;
        __syncthreads();
        const float zt = sred[0][0] + sred[0][1];
        gdp = (zt > vencur) ? d : 0.0f;
        gamp = sGam[0];
        vcur = sV[1][i];
        vencur = sVen[1];
    }

    // ---- main loop t = 1 .. LM1-1 ----------------------------------------
    for (int t = 1; t < LM1; t++) {
        const int ph = t & 31;
        if (ph == 1) {                       // stage next chunk (slots now free)
            const int qn = (t >> 5) + 1;
            if (qn < 32) stage(qn);
        }
        if (ph == 31) {                      // next step crosses into new chunk
            asm volatile("cp.async.wait_group 0;" ::: "memory");
            __syncthreads();
        }

        const int su = (t - 1) & 63;
        const int sp = (t + 1) & 63;
        const float4* ku = reinterpret_cast<const float4*>(sK[su]);
        const float4* kp = reinterpret_cast<const float4*>(sK[sp]);

        // ---- batch (independent of this step's gate) ----
        // M += gd_{t-1} (x) kn_{t-1}
        const float2 gg = make_float2(gdp, gdp);
        #pragma unroll
        for (int c = 0; c < 16; c++) {
            const float4 a = ku[c];
            M[2 * c]     = fma2(gg, make_float2(a.x, a.y), M[2 * c]);
            M[2 * c + 1] = fma2(gg, make_float2(a.z, a.w), M[2 * c + 1]);
        }
        // pre_{t+1} = M_{t-1} . kn_{t+1}
        float2 p0 = make_float2(0.f, 0.f), p1 = p0, p2 = p0, p3 = p0;
        #pragma unroll
        for (int c = 0; c < 16; c += 2) {
            const float4 a = kp[c];
            const float4 bq = kp[c + 1];
            p0 = fma2(M[2 * c],     make_float2(a.x, a.y),  p0);
            p1 = fma2(M[2 * c + 1], make_float2(a.z, a.w),  p1);
            p2 = fma2(M[2 * c + 2], make_float2(bq.x, bq.y), p2);
            p3 = fma2(M[2 * c + 3], make_float2(bq.z, bq.w), p3);
        }
        const float pre_next = ((p0.x + p0.y) + (p1.x + p1.y)) + ((p2.x + p2.y) + (p3.x + p3.y));
        // prefetch next serial operands
        const float vnext = sV[sp][i];
        const float vennext = sVen[sp];

        // ---- serial chain ----
        const float vp = fmaf(gamp, gdp, pre);
        const float d = vcur - vp;
        float z = d * d;
        z += __shfl_xor_sync(0xffffffffu, z, 1);
        z += __shfl_xor_sync(0xffffffffu, z, 2);
        z += __shfl_xor_sync(0xffffffffu, z, 4);
        z += __shfl_xor_sync(0xffffffffu, z, 8);
        z += __shfl_xor_sync(0xffffffffu, z, 16);
        if (lane == 0) sred[t & 1][w] = z;
        __syncthreads();
        const float zt = sred[t & 1][0] + sred[t & 1][1];
        const float gd = (zt > vencur) ? d : 0.0f;

        // rotate
        pre = pre_next; gdp = gd; gamp = sGam[t & 63];
        vcur = vnext; vencur = vennext;
    }

    // final deferred update: M += gd_{LM1-1} (x) kn_{LM1-1}
    {
        const float4* ku = reinterpret_cast<const float4*>(sK[(LM1 - 1) & 63]);
        const float2 gg = make_float2(gdp, gdp);
        #pragma unroll
        for (int c = 0; c < 16; c++) {
            const float4 a = ku[c];
            M[2 * c]     = fma2(gg, make_float2(a.x, a.y), M[2 * c]);
            M[2 * c + 1] = fma2(gg, make_float2(a.z, a.w), M[2 * c + 1]);
        }
    }

    // -------- epilogue: r = (M q) @ rp_W + rp_b ; out = r @ out_W + out_b --
    __syncthreads();
    sq[i] = g_q[(b << 6) + i];
    __syncthreads();
    float mq;
    {
        const float4* qp = reinterpret_cast<const float4*>(sq);
        float2 p0 = make_float2(0.f, 0.f), p1 = p0, p2 = p0, p3 = p0;
        #pragma unroll
        for (int c = 0; c < 16; c += 2) {
            const float4 wa = qp[c];
            const float4 wb = qp[c + 1];
            p0 = fma2(M[2 * c],     make_float2(wa.x, wa.y), p0);
            p1 = fma2(M[2 * c + 1], make_float2(wa.z, wa.w), p1);
            p2 = fma2(M[2 * c + 2], make_float2(wb.x, wb.y), p2);
            p3 = fma2(M[2 * c + 3], make_float2(wb.z, wb.w), p3);
        }
        mq = ((p0.x + p0.y) + (p1.x + p1.y)) + ((p2.x + p2.y) + (p3.x + p3.y));
    }
    __syncthreads();
    sr[i] = mq;
    __syncthreads();
    float r = rpb[i];
    for (int j = 0; j < 64; j++) r = fmaf(sr[j], rpW[j * 64 + i], r);
    __syncthreads();
    sr[i] = r;
    __syncthreads();
    float o = outb[i];
    for (int j = 0; j < 64; j++) o = fmaf(sr[j], outW[j * 64 + i], o);
    out[(b << 6) + i] = o;
}

// ---------------------------------------------------------------------------
extern "C" void kernel_launch(void* const* d_in, const int* in_sizes, int n_in,
                              void* d_out, int out_size)
{
    const int*   seq    = (const int*)  d_in[0];
    const float* embedW = (const float*)d_in[1];
    const float* W1     = (const float*)d_in[2];
    const float* b1     = (const float*)d_in[3];
    const float* W2     = (const float*)d_in[4];
    const float* b2     = (const float*)d_in[5];
    const float* lng    = (const float*)d_in[6];
    const float* lnb    = (const float*)d_in[7];
    const float* kpW    = (const float*)d_in[8];
    const float* vpW    = (const float*)d_in[9];
    const float* qpW    = (const float*)d_in[10];
    const float* rpW    = (const float*)d_in[11];
    const float* rpb    = (const float*)d_in[12];
    const float* outW   = (const float*)d_in[13];
    const float* outb   = (const float*)d_in[14];
    float* out = (float*)d_out;

    const int smem = 28992 * (int)sizeof(float);   // 115968 B
    cudaFuncSetAttribute(k_tokens, cudaFuncAttributeMaxDynamicSharedMemorySize, smem);

    k_tokens<<<256, 256, smem>>>(seq, embedW, W1, b1, W2, b2, lng, lnb, kpW, vpW, qpW);
    k_gamma<<<256, 256>>>();
    k_scan<<<64, 64>>>(rpW, rpb, outW, outb, out);
}